// round 1
// baseline (speedup 1.0000x reference)
#include <cuda_runtime.h>
#include <cuda_bf16.h>

#define BB 16
#define NN 8192
#define SS 1024
#define KK 32

// ---------------- scratch (no allocs allowed) ----------------
__device__ float  g_newxyz[BB * SS * 3];   // FPS-selected centers
__device__ float  g_gmax[BB * SS * 3];     // max over K of diff, per coord
__device__ float  g_gsum[BB * SS * 3];     // sum over K of diff, per coord
__device__ double g_acc[2];                // sum(diff), sum(diff^2) for global std
__device__ float  g_lc[BB * 6 * SS];       // pooled features

// =====================================================================
// K1: Farthest point sampling. 16 blocks x 512 threads, 16 pts/thread in
// registers. Exact replication of the reference math:
//   d = ((dx*dx + dy*dy) + dz*dz)   (no fma contraction)
//   distance = min(distance, d); argmax with first-index tie-break.
// =====================================================================
__global__ void __launch_bounds__(512) fps_kernel(const float* __restrict__ xyz)
{
    const int b = blockIdx.x;
    const int t = threadIdx.x;
    const float* X = xyz + (size_t)b * NN * 3;

    float px[16], py[16], pz[16], dist[16];
#pragma unroll
    for (int i = 0; i < 16; i++) {
        int p = t + 512 * i;
        px[i] = X[p * 3 + 0];
        py[i] = X[p * 3 + 1];
        pz[i] = X[p * 3 + 2];
        dist[i] = 1e10f;
    }

    __shared__ unsigned long long s_max[2];
    __shared__ float s_cen[3];

    if (t == 0) {
        s_max[0] = 0ull;
        s_max[1] = 0ull;
        if (b == 0) { g_acc[0] = 0.0; g_acc[1] = 0.0; }  // reset per replay
        // sample 0 is point index 0 (deterministic start, as in reference)
        s_cen[0] = px[0]; s_cen[1] = py[0]; s_cen[2] = pz[0];
        float* o = g_newxyz + (size_t)(b * SS) * 3;
        o[0] = px[0]; o[1] = py[0]; o[2] = pz[0];
    }
    __syncthreads();

    for (int s = 0; s < SS - 1; s++) {
        const float cx = s_cen[0], cy = s_cen[1], cz = s_cen[2];

        float bestv = -1.0f;
        int   besti = 0;
#pragma unroll
        for (int i = 0; i < 16; i++) {
            float dx = __fsub_rn(px[i], cx);
            float dy = __fsub_rn(py[i], cy);
            float dz = __fsub_rn(pz[i], cz);
            float d  = __fadd_rn(__fadd_rn(__fmul_rn(dx, dx), __fmul_rn(dy, dy)),
                                 __fmul_rn(dz, dz));
            float nd = fminf(dist[i], d);
            dist[i] = nd;
            if (nd > bestv) { bestv = nd; besti = t + 512 * i; }  // strict > keeps lowest idx
        }
        // distances >= 0 -> float bits are order-preserving; ~idx -> lowest idx on tie
        unsigned long long pk =
            ((unsigned long long)__float_as_uint(bestv) << 32) |
            (unsigned long long)(0xFFFFFFFFu - (unsigned)besti);
#pragma unroll
        for (int o = 16; o > 0; o >>= 1) {
            unsigned long long q = __shfl_down_sync(0xFFFFFFFFu, pk, o);
            if (q > pk) pk = q;
        }
        if ((t & 31) == 0) atomicMax(&s_max[s & 1], pk);
        if (t == 0) s_max[(s + 1) & 1] = 0ull;
        __syncthreads();

        unsigned long long w = s_max[s & 1];
        int widx = (int)(0xFFFFFFFFu - (unsigned)(w & 0xFFFFFFFFull));
        if ((widx & 511) == t) {  // owner thread publishes the new centroid
            int i = widx >> 9;
            float ax = px[i], ay = py[i], az = pz[i];
            s_cen[0] = ax; s_cen[1] = ay; s_cen[2] = az;
            float* o = g_newxyz + (size_t)(b * SS + s + 1) * 3;
            o[0] = ax; o[1] = ay; o[2] = az;
        }
        __syncthreads();
    }
}

// =====================================================================
// K2: kNN (K=32) + group stats. Warp per query, streaming top-32 with one
// list element per lane. Distance matches reference square_distance form:
//   d = ((-2*dot) + |c|^2) + |p|^2, dot = ((x*cx + y*cy) + z*cz)
// Tie handling == lax.top_k: insert on strict <, evict highest-index max,
// process candidates in ascending index order.
// =====================================================================
__global__ void __launch_bounds__(256) knn_kernel(const float* __restrict__ xyz)
{
    extern __shared__ float sm[];
    float* sx = sm;
    float* sy = sm + NN;
    float* sz = sm + 2 * NN;
    float* sq = sm + 3 * NN;

    const int b  = blockIdx.x >> 4;   // 16 query-chunks per batch
    const int qc = blockIdx.x & 15;
    const float* X = xyz + (size_t)b * NN * 3;

    for (int p = threadIdx.x; p < NN; p += 256) {
        float x = X[p * 3], y = X[p * 3 + 1], z = X[p * 3 + 2];
        sx[p] = x; sy[p] = y; sz[p] = z;
        sq[p] = __fadd_rn(__fadd_rn(__fmul_rn(x, x), __fmul_rn(y, y)), __fmul_rn(z, z));
    }
    __syncthreads();

    const int warp = threadIdx.x >> 5;
    const int lane = threadIdx.x & 31;

    for (int qi = 0; qi < 8; qi++) {
        const int s = qc * 64 + warp * 8 + qi;
        const float* cen = g_newxyz + (size_t)(b * SS + s) * 3;
        const float cx = cen[0], cy = cen[1], cz = cen[2];
        const float csq = __fadd_rn(__fadd_rn(__fmul_rn(cx, cx), __fmul_rn(cy, cy)),
                                    __fmul_rn(cz, cz));

        // fill with candidates 0..31
        int   ki = lane;
        float kd;
        {
            float dot = __fadd_rn(__fadd_rn(__fmul_rn(sx[lane], cx), __fmul_rn(sy[lane], cy)),
                                  __fmul_rn(sz[lane], cz));
            kd = __fadd_rn(__fadd_rn(__fmul_rn(-2.0f, dot), csq), sq[lane]);
        }
        // current max of list (value, index); on value tie prefer HIGHER index (the evictee)
        float mv = kd; int mi = ki;
#pragma unroll
        for (int o = 16; o; o >>= 1) {
            float qv = __shfl_down_sync(0xFFFFFFFFu, mv, o);
            int   qj = __shfl_down_sync(0xFFFFFFFFu, mi, o);
            if (qv > mv || (qv == mv && qj > mi)) { mv = qv; mi = qj; }
        }
        mv = __shfl_sync(0xFFFFFFFFu, mv, 0);
        mi = __shfl_sync(0xFFFFFFFFu, mi, 0);

        for (int base = 32; base < NN; base += 32) {
            const int p = base + lane;
            float dot = __fadd_rn(__fadd_rn(__fmul_rn(sx[p], cx), __fmul_rn(sy[p], cy)),
                                  __fmul_rn(sz[p], cz));
            float d = __fadd_rn(__fadd_rn(__fmul_rn(-2.0f, dot), csq), sq[p]);

            unsigned mask = __ballot_sync(0xFFFFFFFFu, d < mv);
            while (mask) {
                int src = __ffs(mask) - 1;   // ascending index order
                mask &= mask - 1;
                float dn = __shfl_sync(0xFFFFFFFFu, d, src);
                int   pn = base + src;
                if (ki == mi) { kd = dn; ki = pn; }   // evict current max owner
                mv = kd; mi = ki;
#pragma unroll
                for (int o = 16; o; o >>= 1) {
                    float qv = __shfl_down_sync(0xFFFFFFFFu, mv, o);
                    int   qj = __shfl_down_sync(0xFFFFFFFFu, mi, o);
                    if (qv > mv || (qv == mv && qj > mi)) { mv = qv; mi = qj; }
                }
                mv = __shfl_sync(0xFFFFFFFFu, mv, 0);
                mi = __shfl_sync(0xFFFFFFFFu, mi, 0);
                mask &= __ballot_sync(0xFFFFFFFFu, d < mv);
            }
        }

        // group stats over the 32 kept neighbors
        float dx = __fsub_rn(sx[ki], cx);
        float dy = __fsub_rn(sy[ki], cy);
        float dz = __fsub_rn(sz[ki], cz);
        float sdx = dx, sdy = dy, sdz = dz;
        float mdx = dx, mdy = dy, mdz = dz;
        float s1 = dx + dy + dz;
        float s2 = dx * dx + dy * dy + dz * dz;
#pragma unroll
        for (int o = 16; o; o >>= 1) {
            sdx += __shfl_down_sync(0xFFFFFFFFu, sdx, o);
            sdy += __shfl_down_sync(0xFFFFFFFFu, sdy, o);
            sdz += __shfl_down_sync(0xFFFFFFFFu, sdz, o);
            mdx = fmaxf(mdx, __shfl_down_sync(0xFFFFFFFFu, mdx, o));
            mdy = fmaxf(mdy, __shfl_down_sync(0xFFFFFFFFu, mdy, o));
            mdz = fmaxf(mdz, __shfl_down_sync(0xFFFFFFFFu, mdz, o));
            s1 += __shfl_down_sync(0xFFFFFFFFu, s1, o);
            s2 += __shfl_down_sync(0xFFFFFFFFu, s2, o);
        }
        if (lane == 0) {
            int ix = (b * SS + s) * 3;
            g_gsum[ix] = sdx; g_gsum[ix + 1] = sdy; g_gsum[ix + 2] = sdz;
            g_gmax[ix] = mdx; g_gmax[ix + 1] = mdy; g_gmax[ix + 2] = mdz;
            atomicAdd(&g_acc[0], (double)s1);
            atomicAdd(&g_acc[1], (double)s2);
        }
    }
}

// =====================================================================
// K3: std, lc, BN1+relu, safe_cdist, BN2+relu. Single block (BN needs
// global stats anyway; total work is tiny).
// =====================================================================
__global__ void __launch_bounds__(1024) finalize_kernel(
    const float* __restrict__ bn1g, const float* __restrict__ bn1b,
    const float* __restrict__ bn2g, const float* __restrict__ bn2b,
    float* __restrict__ out)
{
    const int t = threadIdx.x;
    const int lane = t & 31, warp = t >> 5;

    __shared__ float s_red[32];
    __shared__ float s_se;            // std + 1e-5
    __shared__ float s_mean[6], s_var[6];
    __shared__ float s_tf[BB * 36];
    __shared__ float s_m2[36], s_v2[36];

    if (t == 0) {
        double M = (double)BB * SS * KK * 3;
        double mean = g_acc[0] / M;
        double var = (g_acc[1] - g_acc[0] * g_acc[0] / M) / (M - 1.0); // ddof=1
        (void)mean;
        s_se = (float)sqrt(var) + 1e-5f;
    }
    __syncthreads();
    const float se = s_se;

    // lc: channels 0..2 = max_k(diff)/se + mean_k(diff)/se ; 3..5 = 2*center
    for (int idx = t; idx < BB * SS; idx += 1024) {
        int b = idx >> 10, s = idx & (SS - 1);
        const float* gm = g_gmax + idx * 3;
        const float* gs = g_gsum + idx * 3;
        const float* cn = g_newxyz + idx * 3;
#pragma unroll
        for (int c = 0; c < 3; c++) {
            float mx = __fdiv_rn(gm[c], se);
            float mn = __fdiv_rn(__fdiv_rn(gs[c], 32.0f), se);
            g_lc[(b * 6 + c) * SS + s] = __fadd_rn(mx, mn);
        }
#pragma unroll
        for (int c = 0; c < 3; c++) {
            float v = cn[c];
            g_lc[(b * 6 + 3 + c) * SS + s] = v + v;
        }
    }
    __syncthreads();

    // BN1 stats per channel over (B, S) = 16384 values
    for (int c = 0; c < 6; c++) {
        float part = 0.0f;
        for (int i = t; i < BB * SS; i += 1024) {
            int b = i >> 10, s = i & 1023;
            part += g_lc[(b * 6 + c) * SS + s];
        }
#pragma unroll
        for (int o = 16; o; o >>= 1) part += __shfl_down_sync(0xFFFFFFFFu, part, o);
        if (lane == 0) s_red[warp] = part;
        __syncthreads();
        if (t == 0) {
            float tot = 0.0f;
            for (int w = 0; w < 32; w++) tot += s_red[w];
            s_mean[c] = tot / (float)(BB * SS);
        }
        __syncthreads();
        float m = s_mean[c];
        part = 0.0f;
        for (int i = t; i < BB * SS; i += 1024) {
            int b = i >> 10, s = i & 1023;
            float d = g_lc[(b * 6 + c) * SS + s] - m;
            part += d * d;
        }
#pragma unroll
        for (int o = 16; o; o >>= 1) part += __shfl_down_sync(0xFFFFFFFFu, part, o);
        if (lane == 0) s_red[warp] = part;
        __syncthreads();
        if (t == 0) {
            float tot = 0.0f;
            for (int w = 0; w < 32; w++) tot += s_red[w];
            s_var[c] = tot / (float)(BB * SS);   // biased, as in reference
        }
        __syncthreads();
    }
    // normalize + relu in place
    for (int c = 0; c < 6; c++) {
        float m = s_mean[c], v = s_var[c];
        float g = bn1g[c], bt = bn1b[c];
        float den = sqrtf(v + 1e-5f);
        for (int i = t; i < BB * SS; i += 1024) {
            int b = i >> 10, s = i & 1023;
            int ix = (b * 6 + c) * SS + s;
            float y = (g_lc[ix] - m) / den * g + bt;
            g_lc[ix] = fmaxf(y, 0.0f);
        }
    }
    __syncthreads();

    // safe_cdist: 16 batches x 15 pairs, warp per task; diag = 0
    if (t < BB * 6) {
        int b = t / 6, c = t % 6;
        s_tf[b * 36 + c * 6 + c] = 0.0f;
    }
    for (int task = warp; task < BB * 15; task += 32) {
        int b = task / 15, pr = task % 15;
        int i = 0, j = 0, p = pr;
        for (i = 0; i < 5; i++) {
            int row = 5 - i;
            if (p < row) { j = i + 1 + p; break; }
            p -= row;
        }
        const float* A  = g_lc + (b * 6 + i) * SS;
        const float* Bp = g_lc + (b * 6 + j) * SS;
        float part = 0.0f;
        for (int s = lane; s < SS; s += 32) {
            float d = A[s] - Bp[s];
            part += d * d;
        }
#pragma unroll
        for (int o = 16; o; o >>= 1) part += __shfl_down_sync(0xFFFFFFFFu, part, o);
        if (lane == 0) {
            float v = part > 0.0f ? sqrtf(part) : 0.0f;  // zero-safe sqrt
            s_tf[b * 36 + i * 6 + j] = v;
            s_tf[b * 36 + j * 6 + i] = v;
        }
    }
    __syncthreads();

    // BN2 over batch (16) per feature (36)
    if (t < 36) {
        float m = 0.0f;
        for (int b = 0; b < BB; b++) m += s_tf[b * 36 + t];
        m /= (float)BB;
        float v = 0.0f;
        for (int b = 0; b < BB; b++) {
            float d = s_tf[b * 36 + t] - m;
            v += d * d;
        }
        v /= (float)BB;
        s_m2[t] = m; s_v2[t] = v;
    }
    __syncthreads();
    if (t < BB * 36) {
        int b = t / 36, f = t % 36;
        float x = s_tf[b * 36 + f];
        float y = (x - s_m2[f]) / sqrtf(s_v2[f] + 1e-5f) * bn2g[f] + bn2b[f];
        out[t] = fmaxf(y, 0.0f);
    }
}

// =====================================================================
extern "C" void kernel_launch(void* const* d_in, const int* in_sizes, int n_in,
                              void* d_out, int out_size)
{
    const float* xyz  = (const float*)d_in[0];
    const float* bn1g = (const float*)d_in[1];
    const float* bn1b = (const float*)d_in[2];
    const float* bn2g = (const float*)d_in[3];
    const float* bn2b = (const float*)d_in[4];
    float* out = (float*)d_out;

    static bool attr_set = false;
    // idempotent host-side attribute set (not a stream op; capture-safe)
    cudaFuncSetAttribute(knn_kernel, cudaFuncAttributeMaxDynamicSharedMemorySize,
                         4 * NN * (int)sizeof(float));
    (void)attr_set;

    fps_kernel<<<BB, 512>>>(xyz);
    knn_kernel<<<BB * 16, 256, 4 * NN * sizeof(float)>>>(xyz);
    finalize_kernel<<<1, 1024>>>(bn1g, bn1b, bn2g, bn2b, out);
}

// round 2
// speedup vs baseline: 1.5749x; 1.5749x over previous
#include <cuda_runtime.h>
#include <cuda_bf16.h>

#define BB 16
#define NN 8192
#define SS 1024
#define KK 32
#define FULLMASK 0xFFFFFFFFu

// ---------------- scratch (no allocs allowed) ----------------
__device__ float  g_newxyz[BB * SS * 3];   // FPS-selected centers
__device__ float  g_gmax[BB * SS * 3];     // max over K of diff, per coord
__device__ float  g_gsum[BB * SS * 3];     // sum over K of diff, per coord
__device__ double g_acc[2];                // sum(diff), sum(diff^2) for global std
__device__ float  g_lc[BB * 6 * SS];       // pooled features

// ---------------- f32x2 helpers (Blackwell packed fp32) ----------------
__device__ __forceinline__ unsigned long long pk2(float lo, float hi) {
    unsigned long long r;
    asm("mov.b64 %0, {%1, %2};" : "=l"(r) : "f"(lo), "f"(hi));
    return r;
}
__device__ __forceinline__ void upk2(float& lo, float& hi, unsigned long long v) {
    asm("mov.b64 {%0, %1}, %2;" : "=f"(lo), "=f"(hi) : "l"(v));
}
__device__ __forceinline__ unsigned long long add2(unsigned long long a, unsigned long long b) {
    unsigned long long r;
    asm("add.rn.f32x2 %0, %1, %2;" : "=l"(r) : "l"(a), "l"(b));
    return r;
}
__device__ __forceinline__ unsigned long long mul2(unsigned long long a, unsigned long long b) {
    unsigned long long r;
    asm("mul.rn.f32x2 %0, %1, %2;" : "=l"(r) : "l"(a), "l"(b));
    return r;
}

// =====================================================================
// K1: Farthest point sampling. 16 blocks x 512 threads, 16 pts/thread in
// registers, packed f32x2 math (bitwise identical to scalar rn ops):
//   d = ((dx*dx + dy*dy) + dz*dz), dx = px + (-cx)
//   distance = min(distance, d); argmax with lowest-index tie-break.
// =====================================================================
__global__ void __launch_bounds__(512) fps_kernel(const float* __restrict__ xyz)
{
    const int b = blockIdx.x;
    const int t = threadIdx.x;
    const int lane = t & 31, warp = t >> 5;
    const float* X = xyz + (size_t)b * NN * 3;

    // slot s (0..15) -> point t + 512*s ; pairs (2i, 2i+1) packed
    unsigned long long px2[8], py2[8], pz2[8];
    float dist[16];
#pragma unroll
    for (int i = 0; i < 8; i++) {
        int p0 = t + 512 * (2 * i);
        int p1 = t + 512 * (2 * i + 1);
        px2[i] = pk2(X[p0 * 3 + 0], X[p1 * 3 + 0]);
        py2[i] = pk2(X[p0 * 3 + 1], X[p1 * 3 + 1]);
        pz2[i] = pk2(X[p0 * 3 + 2], X[p1 * 3 + 2]);
        dist[2 * i] = 1e10f;
        dist[2 * i + 1] = 1e10f;
    }

    __shared__ unsigned long long s_cand[16];
    __shared__ float s_cen[3];

    if (t == 0) {
        if (b == 0) { g_acc[0] = 0.0; g_acc[1] = 0.0; }  // reset per replay
        // sample 0 = point index 0 (deterministic start, as in reference)
        float ax = X[0], ay = X[1], az = X[2];
        s_cen[0] = ax; s_cen[1] = ay; s_cen[2] = az;
        float* o = g_newxyz + (size_t)(b * SS) * 3;
        o[0] = ax; o[1] = ay; o[2] = az;
    }
    __syncthreads();

    for (int s = 0; s < SS - 1; s++) {
        const float cx = s_cen[0], cy = s_cen[1], cz = s_cen[2];
        const unsigned long long ncx2 = pk2(-cx, -cx);
        const unsigned long long ncy2 = pk2(-cy, -cy);
        const unsigned long long ncz2 = pk2(-cz, -cz);

        float bestv = -1.0f;
#pragma unroll
        for (int i = 0; i < 8; i++) {
            unsigned long long dx2 = add2(px2[i], ncx2);
            unsigned long long dy2 = add2(py2[i], ncy2);
            unsigned long long dz2 = add2(pz2[i], ncz2);
            unsigned long long d2 = add2(add2(mul2(dx2, dx2), mul2(dy2, dy2)),
                                         mul2(dz2, dz2));
            float d0, d1;
            upk2(d0, d1, d2);
            float n0 = fminf(dist[2 * i], d0);
            float n1 = fminf(dist[2 * i + 1], d1);
            dist[2 * i] = n0;
            dist[2 * i + 1] = n1;
            bestv = fmaxf(bestv, fmaxf(n0, n1));
        }

        // warp max value
        float wmax = bestv;
#pragma unroll
        for (int o = 16; o; o >>= 1)
            wmax = fmaxf(wmax, __shfl_xor_sync(FULLMASK, wmax, o));

        // lowest point index attaining wmax (descending scan -> first match)
        int cand = 0x7FFFFFFF;
#pragma unroll
        for (int sl = 15; sl >= 0; sl--)
            cand = (dist[sl] == wmax) ? (t + (sl << 9)) : cand;
#pragma unroll
        for (int o = 16; o; o >>= 1) {
            int c2 = __shfl_xor_sync(FULLMASK, cand, o);
            cand = c2 < cand ? c2 : cand;
        }
        if (lane == 0)
            s_cand[warp] = ((unsigned long long)__float_as_uint(wmax) << 32) |
                           (unsigned long long)(0xFFFFFFFFu - (unsigned)cand);
        __syncthreads();

        if (warp == 0) {
            unsigned long long v = s_cand[lane & 15];
#pragma unroll
            for (int o = 8; o; o >>= 1) {
                unsigned long long v2 = __shfl_xor_sync(FULLMASK, v, o);
                v = v2 > v ? v2 : v;
            }
            if (lane == 0) {
                int widx = (int)(0xFFFFFFFFu - (unsigned)(v & 0xFFFFFFFFull));
                float ax = X[widx * 3 + 0];
                float ay = X[widx * 3 + 1];
                float az = X[widx * 3 + 2];
                s_cen[0] = ax; s_cen[1] = ay; s_cen[2] = az;
                float* o = g_newxyz + (size_t)(b * SS + s + 1) * 3;
                o[0] = ax; o[1] = ay; o[2] = az;
            }
        }
        __syncthreads();
    }
}

// =====================================================================
// K2: kNN (K=32) + group stats. Warp per query, buffered bitonic top-32.
// key = (orderable(d) << 13) | idx -> ascending u64 order == (d, idx)
// lexicographic order == lax.top_k selection + tie semantics.
// =====================================================================
__device__ __forceinline__ unsigned long long u64min(unsigned long long a,
                                                    unsigned long long b) {
    return a < b ? a : b;
}
__device__ __forceinline__ unsigned long long u64max(unsigned long long a,
                                                    unsigned long long b) {
    return a < b ? b : a;
}
__device__ __forceinline__ unsigned long long makekey(float d, int idx) {
    unsigned ub = __float_as_uint(d);
    ub ^= ((unsigned)((int)ub >> 31)) | 0x80000000u;
    return ((unsigned long long)ub << 13) | (unsigned)idx;
}
// full bitonic sort of 32 keys (one per lane), ascending by lane
__device__ __forceinline__ unsigned long long sort32(unsigned long long key, int lane)
{
#pragma unroll
    for (int k = 2; k <= 32; k <<= 1) {
#pragma unroll
        for (int j = k >> 1; j > 0; j >>= 1) {
            unsigned long long other = __shfl_xor_sync(FULLMASK, key, j);
            bool up = ((lane & k) == 0);
            bool takeMin = (((lane & j) == 0) == up);
            key = takeMin ? u64min(key, other) : u64max(key, other);
        }
    }
    return key;
}
// list (sorted asc) + buffer -> 32 smallest of union, sorted asc
__device__ __forceinline__ unsigned long long merge32(unsigned long long key,
                                                      unsigned long long buf, int lane)
{
    buf = sort32(buf, lane);
    unsigned long long rev = __shfl_sync(FULLMASK, buf, 31 - lane);
    key = u64min(key, rev);             // bitonic sequence of the 32 smallest
#pragma unroll
    for (int j = 16; j > 0; j >>= 1) {  // bitonic clean -> ascending
        unsigned long long other = __shfl_xor_sync(FULLMASK, key, j);
        bool takeMin = ((lane & j) == 0);
        key = takeMin ? u64min(key, other) : u64max(key, other);
    }
    return key;
}

__global__ void __launch_bounds__(512) knn_kernel(const float* __restrict__ xyz)
{
    extern __shared__ float4 spts[];    // [NN] : x, y, z, |p|^2  (128KB)

    const int b  = blockIdx.x >> 4;
    const int qc = blockIdx.x & 15;
    const float* X = xyz + (size_t)b * NN * 3;

    for (int p = threadIdx.x; p < NN; p += 512) {
        float x = X[p * 3], y = X[p * 3 + 1], z = X[p * 3 + 2];
        float sq = __fadd_rn(__fadd_rn(__fmul_rn(x, x), __fmul_rn(y, y)),
                             __fmul_rn(z, z));
        spts[p] = make_float4(x, y, z, sq);
    }
    __syncthreads();

    const int warp = threadIdx.x >> 5;
    const int lane = threadIdx.x & 31;

    for (int qi = 0; qi < 4; qi++) {
        const int s = qc * 64 + warp * 4 + qi;
        const float* cen = g_newxyz + (size_t)(b * SS + s) * 3;
        const float cx = cen[0], cy = cen[1], cz = cen[2];
        const float csq = __fadd_rn(__fadd_rn(__fmul_rn(cx, cx), __fmul_rn(cy, cy)),
                                    __fmul_rn(cz, cz));

        // init list from candidates 0..31
        unsigned long long key;
        {
            float4 pt = spts[lane];
            float dot = __fadd_rn(__fadd_rn(__fmul_rn(pt.x, cx), __fmul_rn(pt.y, cy)),
                                  __fmul_rn(pt.z, cz));
            float d = __fadd_rn(__fadd_rn(__fmul_rn(-2.0f, dot), csq), pt.w);
            key = makekey(d, lane);
        }
        key = sort32(key, lane);
        unsigned long long kth = __shfl_sync(FULLMASK, key, 31);
        unsigned long long buf = ~0ull;
        int bcnt = 0;

        for (int base = 32; base < NN; base += 32) {
            const int p = base + lane;
            float4 pt = spts[p];
            float dot = __fadd_rn(__fadd_rn(__fmul_rn(pt.x, cx), __fmul_rn(pt.y, cy)),
                                  __fmul_rn(pt.z, cz));
            float d = __fadd_rn(__fadd_rn(__fmul_rn(-2.0f, dot), csq), pt.w);
            unsigned long long ck = makekey(d, p);

            unsigned mask = __ballot_sync(FULLMASK, ck < kth);
            while (mask) {
                int src = __ffs(mask) - 1;
                mask &= mask - 1;
                unsigned long long ik = __shfl_sync(FULLMASK, ck, src);
                if (lane == bcnt) buf = ik;
                bcnt++;
                if (bcnt == 32) {
                    key = merge32(key, buf, lane);
                    kth = __shfl_sync(FULLMASK, key, 31);
                    buf = ~0ull;
                    bcnt = 0;
                    mask &= __ballot_sync(FULLMASK, ck < kth);
                }
            }
        }
        if (bcnt > 0) key = merge32(key, buf, lane);   // lanes >= bcnt hold MAX

        // ----- group stats over the kept 32 neighbors -----
        int ki = (int)(key & 0x1FFFull);
        float4 q = spts[ki];
        float dx = __fsub_rn(q.x, cx);
        float dy = __fsub_rn(q.y, cy);
        float dz = __fsub_rn(q.z, cz);
        float sdx = dx, sdy = dy, sdz = dz;
        float mdx = dx, mdy = dy, mdz = dz;
        float s1 = dx + dy + dz;
        float s2 = dx * dx + dy * dy + dz * dz;
#pragma unroll
        for (int o = 16; o; o >>= 1) {
            sdx += __shfl_down_sync(FULLMASK, sdx, o);
            sdy += __shfl_down_sync(FULLMASK, sdy, o);
            sdz += __shfl_down_sync(FULLMASK, sdz, o);
            mdx = fmaxf(mdx, __shfl_down_sync(FULLMASK, mdx, o));
            mdy = fmaxf(mdy, __shfl_down_sync(FULLMASK, mdy, o));
            mdz = fmaxf(mdz, __shfl_down_sync(FULLMASK, mdz, o));
            s1 += __shfl_down_sync(FULLMASK, s1, o);
            s2 += __shfl_down_sync(FULLMASK, s2, o);
        }
        if (lane == 0) {
            int ix = (b * SS + s) * 3;
            g_gsum[ix] = sdx; g_gsum[ix + 1] = sdy; g_gsum[ix + 2] = sdz;
            g_gmax[ix] = mdx; g_gmax[ix + 1] = mdy; g_gmax[ix + 2] = mdz;
            atomicAdd(&g_acc[0], (double)s1);
            atomicAdd(&g_acc[1], (double)s2);
        }
    }
}

// =====================================================================
// K3: std, lc, BN1+relu, safe_cdist, BN2+relu. Single block.
// =====================================================================
__global__ void __launch_bounds__(1024) finalize_kernel(
    const float* __restrict__ bn1g, const float* __restrict__ bn1b,
    const float* __restrict__ bn2g, const float* __restrict__ bn2b,
    float* __restrict__ out)
{
    const int t = threadIdx.x;
    const int lane = t & 31, warp = t >> 5;

    __shared__ float s_red[32];
    __shared__ float s_se;
    __shared__ float s_mean[6], s_var[6];
    __shared__ float s_tf[BB * 36];
    __shared__ float s_m2[36], s_v2[36];

    if (t == 0) {
        double M = (double)BB * SS * KK * 3;
        double var = (g_acc[1] - g_acc[0] * g_acc[0] / M) / (M - 1.0); // ddof=1
        s_se = (float)sqrt(var) + 1e-5f;
    }
    __syncthreads();
    const float se = s_se;

    for (int idx = t; idx < BB * SS; idx += 1024) {
        int b = idx >> 10, s = idx & (SS - 1);
        const float* gm = g_gmax + idx * 3;
        const float* gs = g_gsum + idx * 3;
        const float* cn = g_newxyz + idx * 3;
#pragma unroll
        for (int c = 0; c < 3; c++) {
            float mx = __fdiv_rn(gm[c], se);
            float mn = __fdiv_rn(__fdiv_rn(gs[c], 32.0f), se);
            g_lc[(b * 6 + c) * SS + s] = __fadd_rn(mx, mn);
        }
#pragma unroll
        for (int c = 0; c < 3; c++) {
            float v = cn[c];
            g_lc[(b * 6 + 3 + c) * SS + s] = v + v;
        }
    }
    __syncthreads();

    for (int c = 0; c < 6; c++) {
        float part = 0.0f;
        for (int i = t; i < BB * SS; i += 1024) {
            int b = i >> 10, s = i & 1023;
            part += g_lc[(b * 6 + c) * SS + s];
        }
#pragma unroll
        for (int o = 16; o; o >>= 1) part += __shfl_down_sync(FULLMASK, part, o);
        if (lane == 0) s_red[warp] = part;
        __syncthreads();
        if (t == 0) {
            float tot = 0.0f;
            for (int w = 0; w < 32; w++) tot += s_red[w];
            s_mean[c] = tot / (float)(BB * SS);
        }
        __syncthreads();
        float m = s_mean[c];
        part = 0.0f;
        for (int i = t; i < BB * SS; i += 1024) {
            int b = i >> 10, s = i & 1023;
            float d = g_lc[(b * 6 + c) * SS + s] - m;
            part += d * d;
        }
#pragma unroll
        for (int o = 16; o; o >>= 1) part += __shfl_down_sync(FULLMASK, part, o);
        if (lane == 0) s_red[warp] = part;
        __syncthreads();
        if (t == 0) {
            float tot = 0.0f;
            for (int w = 0; w < 32; w++) tot += s_red[w];
            s_var[c] = tot / (float)(BB * SS);   // biased, as in reference
        }
        __syncthreads();
    }
    for (int c = 0; c < 6; c++) {
        float m = s_mean[c], v = s_var[c];
        float g = bn1g[c], bt = bn1b[c];
        float den = sqrtf(v + 1e-5f);
        for (int i = t; i < BB * SS; i += 1024) {
            int b = i >> 10, s = i & 1023;
            int ix = (b * 6 + c) * SS + s;
            float y = (g_lc[ix] - m) / den * g + bt;
            g_lc[ix] = fmaxf(y, 0.0f);
        }
    }
    __syncthreads();

    if (t < BB * 6) {
        int b = t / 6, c = t % 6;
        s_tf[b * 36 + c * 6 + c] = 0.0f;
    }
    for (int task = warp; task < BB * 15; task += 32) {
        int b = task / 15, pr = task % 15;
        int i = 0, j = 0, p = pr;
        for (i = 0; i < 5; i++) {
            int row = 5 - i;
            if (p < row) { j = i + 1 + p; break; }
            p -= row;
        }
        const float* A  = g_lc + (b * 6 + i) * SS;
        const float* Bp = g_lc + (b * 6 + j) * SS;
        float part = 0.0f;
        for (int s = lane; s < SS; s += 32) {
            float d = A[s] - Bp[s];
            part += d * d;
        }
#pragma unroll
        for (int o = 16; o; o >>= 1) part += __shfl_down_sync(FULLMASK, part, o);
        if (lane == 0) {
            float v = part > 0.0f ? sqrtf(part) : 0.0f;
            s_tf[b * 36 + i * 6 + j] = v;
            s_tf[b * 36 + j * 6 + i] = v;
        }
    }
    __syncthreads();

    if (t < 36) {
        float m = 0.0f;
        for (int b = 0; b < BB; b++) m += s_tf[b * 36 + t];
        m /= (float)BB;
        float v = 0.0f;
        for (int b = 0; b < BB; b++) {
            float d = s_tf[b * 36 + t] - m;
            v += d * d;
        }
        v /= (float)BB;
        s_m2[t] = m; s_v2[t] = v;
    }
    __syncthreads();
    if (t < BB * 36) {
        int b = t / 36, f = t % 36;
        float x = s_tf[b * 36 + f];
        float y = (x - s_m2[f]) / sqrtf(s_v2[f] + 1e-5f) * bn2g[f] + bn2b[f];
        out[t] = fmaxf(y, 0.0f);
    }
}

// =====================================================================
extern "C" void kernel_launch(void* const* d_in, const int* in_sizes, int n_in,
                              void* d_out, int out_size)
{
    const float* xyz  = (const float*)d_in[0];
    const float* bn1g = (const float*)d_in[1];
    const float* bn1b = (const float*)d_in[2];
    const float* bn2g = (const float*)d_in[3];
    const float* bn2b = (const float*)d_in[4];
    float* out = (float*)d_out;

    // idempotent host-side attribute set (capture-safe)
    cudaFuncSetAttribute(knn_kernel, cudaFuncAttributeMaxDynamicSharedMemorySize,
                         NN * (int)sizeof(float4));

    fps_kernel<<<BB, 512>>>(xyz);
    knn_kernel<<<BB * 16, 512, NN * sizeof(float4)>>>(xyz);
    finalize_kernel<<<1, 1024>>>(bn1g, bn1b, bn2g, bn2b, out);
}

// round 3
// speedup vs baseline: 1.9968x; 1.2679x over previous
#include <cuda_runtime.h>
#include <cuda_bf16.h>

#define BB 16
#define NN 8192
#define SS 1024
#define KK 32
#define FULLMASK 0xFFFFFFFFu

// ---------------- scratch (no allocs allowed) ----------------
__device__ float  g_newxyz[BB * SS * 3];   // FPS-selected centers
__device__ float  g_gmax[BB * SS * 3];     // max over K of diff, per coord
__device__ float  g_gsum[BB * SS * 3];     // sum over K of diff, per coord
__device__ double g_acc[2];                // sum(diff), sum(diff^2) for global std
__device__ float  g_lc[BB * 6 * SS];       // pooled features

// ---------------- f32x2 helpers (Blackwell packed fp32) ----------------
__device__ __forceinline__ unsigned long long pk2(float lo, float hi) {
    unsigned long long r;
    asm("mov.b64 %0, {%1, %2};" : "=l"(r) : "f"(lo), "f"(hi));
    return r;
}
__device__ __forceinline__ void upk2(float& lo, float& hi, unsigned long long v) {
    asm("mov.b64 {%0, %1}, %2;" : "=f"(lo), "=f"(hi) : "l"(v));
}
__device__ __forceinline__ unsigned long long add2(unsigned long long a, unsigned long long b) {
    unsigned long long r;
    asm("add.rn.f32x2 %0, %1, %2;" : "=l"(r) : "l"(a), "l"(b));
    return r;
}
__device__ __forceinline__ unsigned long long mul2(unsigned long long a, unsigned long long b) {
    unsigned long long r;
    asm("mul.rn.f32x2 %0, %1, %2;" : "=l"(r) : "l"(a), "l"(b));
    return r;
}

// =====================================================================
// K1: Farthest point sampling. 16 blocks x 512 threads, 16 pts/thread in
// registers, packed f32x2 math (bitwise identical to scalar rn ops):
//   d = ((dx*dx + dy*dy) + dz*dz), dx = px + (-cx)
//   distance = min(distance, d); argmax, lowest-index tie-break.
// Tail: REDUX warp reduces + ONE barrier/step (double-buffered partials,
// every warp redundantly does the cross-warp reduce, centroid via LDG).
// =====================================================================
__global__ void __launch_bounds__(512) fps_kernel(const float* __restrict__ xyz)
{
    const int b = blockIdx.x;
    const int t = threadIdx.x;
    const int lane = t & 31, warp = t >> 5;
    const float* X = xyz + (size_t)b * NN * 3;

    // slot s (0..15) -> point t + 512*s ; pairs (2i, 2i+1) packed
    unsigned long long px2[8], py2[8], pz2[8];
    float dist[16];
#pragma unroll
    for (int i = 0; i < 8; i++) {
        int p0 = t + 512 * (2 * i);
        int p1 = t + 512 * (2 * i + 1);
        px2[i] = pk2(X[p0 * 3 + 0], X[p1 * 3 + 0]);
        py2[i] = pk2(X[p0 * 3 + 1], X[p1 * 3 + 1]);
        pz2[i] = pk2(X[p0 * 3 + 2], X[p1 * 3 + 2]);
        dist[2 * i] = 1e10f;
        dist[2 * i + 1] = 1e10f;
    }

    __shared__ unsigned s_val[2][16];
    __shared__ int      s_idx[2][16];

    if (t == 0 && b == 0) { g_acc[0] = 0.0; g_acc[1] = 0.0; }  // reset per replay
    // sample 0 = point index 0 (deterministic start, as in reference)
    float cx = X[0], cy = X[1], cz = X[2];
    if (t == 0) {
        float* o = g_newxyz + (size_t)(b * SS) * 3;
        o[0] = cx; o[1] = cy; o[2] = cz;
    }

    for (int s = 0; s < SS - 1; s++) {
        const unsigned long long ncx2 = pk2(-cx, -cx);
        const unsigned long long ncy2 = pk2(-cy, -cy);
        const unsigned long long ncz2 = pk2(-cz, -cz);

        float bestv = -1.0f;
#pragma unroll
        for (int i = 0; i < 8; i++) {
            unsigned long long dx2 = add2(px2[i], ncx2);
            unsigned long long dy2 = add2(py2[i], ncy2);
            unsigned long long dz2 = add2(pz2[i], ncz2);
            unsigned long long d2 = add2(add2(mul2(dx2, dx2), mul2(dy2, dy2)),
                                         mul2(dz2, dz2));
            float d0, d1;
            upk2(d0, d1, d2);
            float n0 = fminf(dist[2 * i], d0);
            float n1 = fminf(dist[2 * i + 1], d1);
            dist[2 * i] = n0;
            dist[2 * i + 1] = n1;
            bestv = fmaxf(bestv, fmaxf(n0, n1));
        }

        // warp argmax via REDUX (dists >= 0 -> float order == u32 bit order)
        unsigned wm = __reduce_max_sync(FULLMASK, __float_as_uint(bestv));
        float wmf = __uint_as_float(wm);
        unsigned cand = 0x7FFFFFFFu;
#pragma unroll
        for (int sl = 15; sl >= 0; sl--)
            cand = (dist[sl] == wmf) ? (unsigned)(t + (sl << 9)) : cand;
        cand = __reduce_min_sync(FULLMASK, cand);

        if (lane == 0) { s_val[s & 1][warp] = wm; s_idx[s & 1][warp] = (int)cand; }
        __syncthreads();

        // every warp redundantly reduces the 16 per-warp partials
        unsigned v = s_val[s & 1][lane & 15];
        int      ci = s_idx[s & 1][lane & 15];
        unsigned gm = __reduce_max_sync(FULLMASK, v);
        unsigned c2 = (v == gm) ? (unsigned)ci : 0x7FFFFFFFu;
        int widx = (int)__reduce_min_sync(FULLMASK, c2);

        // centroid via broadcast L1-resident load (96KB batch fits in L1)
        cx = X[widx * 3 + 0];
        cy = X[widx * 3 + 1];
        cz = X[widx * 3 + 2];
        if (t == 0) {
            float* o = g_newxyz + (size_t)(b * SS + s + 1) * 3;
            o[0] = cx; o[1] = cy; o[2] = cz;
        }
    }
}

// =====================================================================
// K2: kNN (K=32) + group stats. Warp per query, buffered bitonic top-32.
// key = (orderable(d) << 13) | idx -> ascending u64 order == (d, idx)
// lexicographic order; selected SET == lax.top_k result (pooling over K
// is order-invariant). 128 blocks (one wave), 8 queries per warp.
// Per-block reduction of std accumulators -> 1 atomicAdd pair per block.
// =====================================================================
__device__ __forceinline__ unsigned long long u64min(unsigned long long a,
                                                    unsigned long long b) {
    return a < b ? a : b;
}
__device__ __forceinline__ unsigned long long u64max(unsigned long long a,
                                                    unsigned long long b) {
    return a < b ? b : a;
}
__device__ __forceinline__ unsigned long long makekey(float d, int idx) {
    unsigned ub = __float_as_uint(d);
    ub ^= ((unsigned)((int)ub >> 31)) | 0x80000000u;
    return ((unsigned long long)ub << 13) | (unsigned)idx;
}
__device__ __forceinline__ unsigned long long sort32(unsigned long long key, int lane)
{
#pragma unroll
    for (int k = 2; k <= 32; k <<= 1) {
#pragma unroll
        for (int j = k >> 1; j > 0; j >>= 1) {
            unsigned long long other = __shfl_xor_sync(FULLMASK, key, j);
            bool up = ((lane & k) == 0);
            bool takeMin = (((lane & j) == 0) == up);
            key = takeMin ? u64min(key, other) : u64max(key, other);
        }
    }
    return key;
}
__device__ __forceinline__ unsigned long long merge32(unsigned long long key,
                                                      unsigned long long buf, int lane)
{
    buf = sort32(buf, lane);
    unsigned long long rev = __shfl_sync(FULLMASK, buf, 31 - lane);
    key = u64min(key, rev);
#pragma unroll
    for (int j = 16; j > 0; j >>= 1) {
        unsigned long long other = __shfl_xor_sync(FULLMASK, key, j);
        bool takeMin = ((lane & j) == 0);
        key = takeMin ? u64min(key, other) : u64max(key, other);
    }
    return key;
}

__global__ void __launch_bounds__(512) knn_kernel(const float* __restrict__ xyz)
{
    extern __shared__ float4 spts[];    // [NN] : x, y, z, |p|^2  (128KB)
    __shared__ double s_p1[16], s_p2[16];

    const int b  = blockIdx.x >> 3;     // 8 query-chunks (128 queries) per batch
    const int qc = blockIdx.x & 7;
    const float* X = xyz + (size_t)b * NN * 3;

    for (int p = threadIdx.x; p < NN; p += 512) {
        float x = X[p * 3], y = X[p * 3 + 1], z = X[p * 3 + 2];
        float sq = __fadd_rn(__fadd_rn(__fmul_rn(x, x), __fmul_rn(y, y)),
                             __fmul_rn(z, z));
        spts[p] = make_float4(x, y, z, sq);
    }
    __syncthreads();

    const int warp = threadIdx.x >> 5;
    const int lane = threadIdx.x & 31;

    double acc1 = 0.0, acc2 = 0.0;      // meaningful on lane 0 only

    for (int qi = 0; qi < 8; qi++) {
        const int s = qc * 128 + warp * 8 + qi;
        const float* cen = g_newxyz + (size_t)(b * SS + s) * 3;
        const float cx = cen[0], cy = cen[1], cz = cen[2];
        const float csq = __fadd_rn(__fadd_rn(__fmul_rn(cx, cx), __fmul_rn(cy, cy)),
                                    __fmul_rn(cz, cz));

        unsigned long long key;
        {
            float4 pt = spts[lane];
            float dot = __fadd_rn(__fadd_rn(__fmul_rn(pt.x, cx), __fmul_rn(pt.y, cy)),
                                  __fmul_rn(pt.z, cz));
            float d = __fadd_rn(__fadd_rn(__fmul_rn(-2.0f, dot), csq), pt.w);
            key = makekey(d, lane);
        }
        key = sort32(key, lane);
        unsigned long long kth = __shfl_sync(FULLMASK, key, 31);
        unsigned long long buf = ~0ull;
        int bcnt = 0;

        for (int base = 32; base < NN; base += 32) {
            const int p = base + lane;
            float4 pt = spts[p];
            float dot = __fadd_rn(__fadd_rn(__fmul_rn(pt.x, cx), __fmul_rn(pt.y, cy)),
                                  __fmul_rn(pt.z, cz));
            float d = __fadd_rn(__fadd_rn(__fmul_rn(-2.0f, dot), csq), pt.w);
            unsigned long long ck = makekey(d, p);

            unsigned mask = __ballot_sync(FULLMASK, ck < kth);
            while (mask) {
                int src = __ffs(mask) - 1;
                mask &= mask - 1;
                unsigned long long ik = __shfl_sync(FULLMASK, ck, src);
                if (lane == bcnt) buf = ik;
                bcnt++;
                if (bcnt == 32) {
                    key = merge32(key, buf, lane);
                    kth = __shfl_sync(FULLMASK, key, 31);
                    buf = ~0ull;
                    bcnt = 0;
                    mask &= __ballot_sync(FULLMASK, ck < kth);
                }
            }
        }
        if (bcnt > 0) key = merge32(key, buf, lane);   // lanes >= bcnt hold MAX

        // ----- group stats over the kept 32 neighbors -----
        int ki = (int)(key & 0x1FFFull);
        float4 q = spts[ki];
        float dx = __fsub_rn(q.x, cx);
        float dy = __fsub_rn(q.y, cy);
        float dz = __fsub_rn(q.z, cz);
        float sdx = dx, sdy = dy, sdz = dz;
        float mdx = dx, mdy = dy, mdz = dz;
        float s1 = dx + dy + dz;
        float s2 = dx * dx + dy * dy + dz * dz;
#pragma unroll
        for (int o = 16; o; o >>= 1) {
            sdx += __shfl_down_sync(FULLMASK, sdx, o);
            sdy += __shfl_down_sync(FULLMASK, sdy, o);
            sdz += __shfl_down_sync(FULLMASK, sdz, o);
            mdx = fmaxf(mdx, __shfl_down_sync(FULLMASK, mdx, o));
            mdy = fmaxf(mdy, __shfl_down_sync(FULLMASK, mdy, o));
            mdz = fmaxf(mdz, __shfl_down_sync(FULLMASK, mdz, o));
            s1 += __shfl_down_sync(FULLMASK, s1, o);
            s2 += __shfl_down_sync(FULLMASK, s2, o);
        }
        if (lane == 0) {
            int ix = (b * SS + s) * 3;
            g_gsum[ix] = sdx; g_gsum[ix + 1] = sdy; g_gsum[ix + 2] = sdz;
            g_gmax[ix] = mdx; g_gmax[ix + 1] = mdy; g_gmax[ix + 2] = mdz;
            acc1 += (double)s1;
            acc2 += (double)s2;
        }
    }

    // one atomicAdd pair per block
    if (lane == 0) { s_p1[warp] = acc1; s_p2[warp] = acc2; }
    __syncthreads();
    if (threadIdx.x == 0) {
        double a = 0.0, c = 0.0;
        for (int w = 0; w < 16; w++) { a += s_p1[w]; c += s_p2[w]; }
        atomicAdd(&g_acc[0], a);
        atomicAdd(&g_acc[1], c);
    }
}

// =====================================================================
// K3: std, lc, BN1+relu, safe_cdist, BN2+relu. Single block.
// =====================================================================
__global__ void __launch_bounds__(1024) finalize_kernel(
    const float* __restrict__ bn1g, const float* __restrict__ bn1b,
    const float* __restrict__ bn2g, const float* __restrict__ bn2b,
    float* __restrict__ out)
{
    const int t = threadIdx.x;
    const int lane = t & 31, warp = t >> 5;

    __shared__ float s_red[32];
    __shared__ float s_se;
    __shared__ float s_mean[6], s_var[6];
    __shared__ float s_tf[BB * 36];
    __shared__ float s_m2[36], s_v2[36];

    if (t == 0) {
        double M = (double)BB * SS * KK * 3;
        double var = (g_acc[1] - g_acc[0] * g_acc[0] / M) / (M - 1.0); // ddof=1
        s_se = (float)sqrt(var) + 1e-5f;
    }
    __syncthreads();
    const float se = s_se;

    for (int idx = t; idx < BB * SS; idx += 1024) {
        int b = idx >> 10, s = idx & (SS - 1);
        const float* gm = g_gmax + idx * 3;
        const float* gs = g_gsum + idx * 3;
        const float* cn = g_newxyz + idx * 3;
#pragma unroll
        for (int c = 0; c < 3; c++) {
            float mx = __fdiv_rn(gm[c], se);
            float mn = __fdiv_rn(__fdiv_rn(gs[c], 32.0f), se);
            g_lc[(b * 6 + c) * SS + s] = __fadd_rn(mx, mn);
        }
#pragma unroll
        for (int c = 0; c < 3; c++) {
            float v = cn[c];
            g_lc[(b * 6 + 3 + c) * SS + s] = v + v;
        }
    }
    __syncthreads();

    for (int c = 0; c < 6; c++) {
        float part = 0.0f;
        for (int i = t; i < BB * SS; i += 1024) {
            int b = i >> 10, s = i & 1023;
            part += g_lc[(b * 6 + c) * SS + s];
        }
#pragma unroll
        for (int o = 16; o; o >>= 1) part += __shfl_down_sync(FULLMASK, part, o);
        if (lane == 0) s_red[warp] = part;
        __syncthreads();
        if (t == 0) {
            float tot = 0.0f;
            for (int w = 0; w < 32; w++) tot += s_red[w];
            s_mean[c] = tot / (float)(BB * SS);
        }
        __syncthreads();
        float m = s_mean[c];
        part = 0.0f;
        for (int i = t; i < BB * SS; i += 1024) {
            int b = i >> 10, s = i & 1023;
            float d = g_lc[(b * 6 + c) * SS + s] - m;
            part += d * d;
        }
#pragma unroll
        for (int o = 16; o; o >>= 1) part += __shfl_down_sync(FULLMASK, part, o);
        if (lane == 0) s_red[warp] = part;
        __syncthreads();
        if (t == 0) {
            float tot = 0.0f;
            for (int w = 0; w < 32; w++) tot += s_red[w];
            s_var[c] = tot / (float)(BB * SS);   // biased, as in reference
        }
        __syncthreads();
    }
    for (int c = 0; c < 6; c++) {
        float m = s_mean[c], v = s_var[c];
        float g = bn1g[c], bt = bn1b[c];
        float den = sqrtf(v + 1e-5f);
        for (int i = t; i < BB * SS; i += 1024) {
            int b = i >> 10, s = i & 1023;
            int ix = (b * 6 + c) * SS + s;
            float y = (g_lc[ix] - m) / den * g + bt;
            g_lc[ix] = fmaxf(y, 0.0f);
        }
    }
    __syncthreads();

    if (t < BB * 6) {
        int b = t / 6, c = t % 6;
        s_tf[b * 36 + c * 6 + c] = 0.0f;
    }
    for (int task = warp; task < BB * 15; task += 32) {
        int b = task / 15, pr = task % 15;
        int i = 0, j = 0, p = pr;
        for (i = 0; i < 5; i++) {
            int row = 5 - i;
            if (p < row) { j = i + 1 + p; break; }
            p -= row;
        }
        const float* A  = g_lc + (b * 6 + i) * SS;
        const float* Bp = g_lc + (b * 6 + j) * SS;
        float part = 0.0f;
        for (int s = lane; s < SS; s += 32) {
            float d = A[s] - Bp[s];
            part += d * d;
        }
#pragma unroll
        for (int o = 16; o; o >>= 1) part += __shfl_down_sync(FULLMASK, part, o);
        if (lane == 0) {
            float v = part > 0.0f ? sqrtf(part) : 0.0f;
            s_tf[b * 36 + i * 6 + j] = v;
            s_tf[b * 36 + j * 6 + i] = v;
        }
    }
    __syncthreads();

    if (t < 36) {
        float m = 0.0f;
        for (int b = 0; b < BB; b++) m += s_tf[b * 36 + t];
        m /= (float)BB;
        float v = 0.0f;
        for (int b = 0; b < BB; b++) {
            float d = s_tf[b * 36 + t] - m;
            v += d * d;
        }
        v /= (float)BB;
        s_m2[t] = m; s_v2[t] = v;
    }
    __syncthreads();
    if (t < BB * 36) {
        int b = t / 36, f = t % 36;
        float x = s_tf[b * 36 + f];
        float y = (x - s_m2[f]) / sqrtf(s_v2[f] + 1e-5f) * bn2g[f] + bn2b[f];
        out[t] = fmaxf(y, 0.0f);
    }
}

// =====================================================================
extern "C" void kernel_launch(void* const* d_in, const int* in_sizes, int n_in,
                              void* d_out, int out_size)
{
    const float* xyz  = (const float*)d_in[0];
    const float* bn1g = (const float*)d_in[1];
    const float* bn1b = (const float*)d_in[2];
    const float* bn2g = (const float*)d_in[3];
    const float* bn2b = (const float*)d_in[4];
    float* out = (float*)d_out;

    // idempotent host-side attribute set (capture-safe)
    cudaFuncSetAttribute(knn_kernel, cudaFuncAttributeMaxDynamicSharedMemorySize,
                         NN * (int)sizeof(float4));

    fps_kernel<<<BB, 512>>>(xyz);
    knn_kernel<<<BB * 8, 512, NN * sizeof(float4)>>>(xyz);
    finalize_kernel<<<1, 1024>>>(bn1g, bn1b, bn2g, bn2b, out);
}

// round 4
// speedup vs baseline: 2.0664x; 1.0348x over previous
#include <cuda_runtime.h>
#include <cuda_bf16.h>

#define BB 16
#define NN 8192
#define SS 1024
#define KK 32
#define FULLMASK 0xFFFFFFFFu
typedef unsigned long long ull;

// ---------------- scratch (no allocs allowed) ----------------
__device__ float  g_newxyz[BB * SS * 3];   // FPS-selected centers
__device__ float  g_gmax[BB * SS * 3];     // max over K of diff, per coord
__device__ float  g_gsum[BB * SS * 3];     // sum over K of diff, per coord
__device__ double g_acc[2];                // sum(diff), sum(diff^2) for global std
__device__ float  g_lc[BB * 6 * SS];       // pooled features

// ---------------- f32x2 helpers (Blackwell packed fp32) ----------------
__device__ __forceinline__ ull pk2(float lo, float hi) {
    ull r;
    asm("mov.b64 %0, {%1, %2};" : "=l"(r) : "f"(lo), "f"(hi));
    return r;
}
__device__ __forceinline__ void upk2(float& lo, float& hi, ull v) {
    asm("mov.b64 {%0, %1}, %2;" : "=f"(lo), "=f"(hi) : "l"(v));
}
__device__ __forceinline__ ull add2(ull a, ull b) {
    ull r;
    asm("add.rn.f32x2 %0, %1, %2;" : "=l"(r) : "l"(a), "l"(b));
    return r;
}
__device__ __forceinline__ ull mul2(ull a, ull b) {
    ull r;
    asm("mul.rn.f32x2 %0, %1, %2;" : "=l"(r) : "l"(a), "l"(b));
    return r;
}

// =====================================================================
// K1: FPS. 16 blocks x 1024 threads, 8 pts/thread in registers, packed
// f32x2 math (bitwise identical to scalar rn ops):
//   d = ((dx*dx + dy*dy) + dz*dz), dx = px + (-cx)
//   distance = min(distance, d); argmax, lowest-index tie-break.
// REDUX warp reduces, ONE barrier/step (double-buffered partials, every
// warp redundantly cross-reduces, centroid via L1-resident LDG).
// =====================================================================
__global__ void __launch_bounds__(1024) fps_kernel(const float* __restrict__ xyz)
{
    const int b = blockIdx.x;
    const int t = threadIdx.x;
    const int lane = t & 31, warp = t >> 5;
    const float* X = xyz + (size_t)b * NN * 3;

    // slot s (0..7) -> point t + 1024*s ; pairs (2i, 2i+1) packed
    ull px2[4], py2[4], pz2[4];
    float dist[8];
#pragma unroll
    for (int i = 0; i < 4; i++) {
        int p0 = t + 1024 * (2 * i);
        int p1 = t + 1024 * (2 * i + 1);
        px2[i] = pk2(X[p0 * 3 + 0], X[p1 * 3 + 0]);
        py2[i] = pk2(X[p0 * 3 + 1], X[p1 * 3 + 1]);
        pz2[i] = pk2(X[p0 * 3 + 2], X[p1 * 3 + 2]);
        dist[2 * i] = 1e10f;
        dist[2 * i + 1] = 1e10f;
    }

    __shared__ unsigned s_val[2][32];
    __shared__ int      s_idx[2][32];

    if (t == 0 && b == 0) { g_acc[0] = 0.0; g_acc[1] = 0.0; }  // reset per replay
    // sample 0 = point index 0 (deterministic start, as in reference)
    float cx = X[0], cy = X[1], cz = X[2];
    if (t == 0) {
        float* o = g_newxyz + (size_t)(b * SS) * 3;
        o[0] = cx; o[1] = cy; o[2] = cz;
    }

    for (int s = 0; s < SS - 1; s++) {
        const ull ncx2 = pk2(-cx, -cx);
        const ull ncy2 = pk2(-cy, -cy);
        const ull ncz2 = pk2(-cz, -cz);

        float bestv = -1.0f;
#pragma unroll
        for (int i = 0; i < 4; i++) {
            ull dx2 = add2(px2[i], ncx2);
            ull dy2 = add2(py2[i], ncy2);
            ull dz2 = add2(pz2[i], ncz2);
            ull d2 = add2(add2(mul2(dx2, dx2), mul2(dy2, dy2)), mul2(dz2, dz2));
            float d0, d1;
            upk2(d0, d1, d2);
            float n0 = fminf(dist[2 * i], d0);
            float n1 = fminf(dist[2 * i + 1], d1);
            dist[2 * i] = n0;
            dist[2 * i + 1] = n1;
            bestv = fmaxf(bestv, fmaxf(n0, n1));
        }

        // warp argmax via REDUX (dists >= 0 -> float order == u32 bit order)
        unsigned wm = __reduce_max_sync(FULLMASK, __float_as_uint(bestv));
        float wmf = __uint_as_float(wm);
        unsigned cand = 0x7FFFFFFFu;
#pragma unroll
        for (int sl = 7; sl >= 0; sl--)
            cand = (dist[sl] == wmf) ? (unsigned)(t + (sl << 10)) : cand;
        cand = __reduce_min_sync(FULLMASK, cand);

        if (lane == 0) { s_val[s & 1][warp] = wm; s_idx[s & 1][warp] = (int)cand; }
        __syncthreads();

        // every warp redundantly reduces the 32 per-warp partials
        unsigned v = s_val[s & 1][lane];
        int      ci = s_idx[s & 1][lane];
        unsigned gm = __reduce_max_sync(FULLMASK, v);
        unsigned c2 = (v == gm) ? (unsigned)ci : 0x7FFFFFFFu;
        int widx = (int)__reduce_min_sync(FULLMASK, c2);

        // centroid via broadcast L1-resident load (96KB batch fits in L1)
        cx = X[widx * 3 + 0];
        cy = X[widx * 3 + 1];
        cz = X[widx * 3 + 2];
        if (t == 0) {
            float* o = g_newxyz + (size_t)(b * SS + s + 1) * 3;
            o[0] = cx; o[1] = cy; o[2] = cz;
        }
    }
}

// =====================================================================
// K2: kNN (K=32) + group stats. Warp per query, buffered bitonic top-32.
// key = (orderable(d) << 13) | idx -> ascending u64 order == (d, idx)
// lexicographic order; selected SET == lax.top_k result (pooling over K
// is order-invariant). 128 blocks x 1024 threads, 4 queries per warp.
// Candidates processed 2/lane (64/chunk) with packed f32x2 distances
// (bitwise identical rounding). Buffer inserts are rank-based: one
// popc+fns+shfl per chunk instead of a serial per-insert loop.
// =====================================================================
__device__ __forceinline__ ull u64min(ull a, ull b) { return a < b ? a : b; }
__device__ __forceinline__ ull u64max(ull a, ull b) { return a < b ? b : a; }
__device__ __forceinline__ ull makekey(float d, int idx) {
    unsigned ub = __float_as_uint(d);
    ub ^= ((unsigned)((int)ub >> 31)) | 0x80000000u;
    return ((ull)ub << 13) | (unsigned)idx;
}
__device__ __forceinline__ ull sort32(ull key, int lane)
{
#pragma unroll
    for (int k = 2; k <= 32; k <<= 1) {
#pragma unroll
        for (int j = k >> 1; j > 0; j >>= 1) {
            ull other = __shfl_xor_sync(FULLMASK, key, j);
            bool up = ((lane & k) == 0);
            bool takeMin = (((lane & j) == 0) == up);
            key = takeMin ? u64min(key, other) : u64max(key, other);
        }
    }
    return key;
}
__device__ __forceinline__ ull merge32(ull key, ull buf, int lane)
{
    buf = sort32(buf, lane);
    ull rev = __shfl_sync(FULLMASK, buf, 31 - lane);
    key = u64min(key, rev);
#pragma unroll
    for (int j = 16; j > 0; j >>= 1) {
        ull other = __shfl_xor_sync(FULLMASK, key, j);
        bool takeMin = ((lane & j) == 0);
        key = takeMin ? u64min(key, other) : u64max(key, other);
    }
    return key;
}
// push all candidates flagged in m (uniform) into buffer by rank; merge on fill
__device__ __forceinline__ void push_chunk(ull ck, unsigned m, int lane,
                                           ull& key, ull& kth, ull& buf, int& bcnt)
{
    int cnt = __popc(m);
    int r = lane - bcnt;
    bool take = (r >= 0) && (r < cnt);
    unsigned pos = __fns(m, 0, take ? (r + 1) : 1);
    ull got = __shfl_sync(FULLMASK, ck, pos & 31);
    if (take) buf = got;
    bcnt += cnt;
    if (bcnt >= 32) {
        key = merge32(key, buf, lane);
        kth = __shfl_sync(FULLMASK, key, 31);
        int left = bcnt - 32;
        buf = ~0ull;
        if (left) {   // re-push overflow candidates (extra entries are harmless)
            int start = cnt - left;
            bool tk2 = lane < left;
            unsigned pos2 = __fns(m, 0, tk2 ? (start + lane + 1) : 1);
            ull got2 = __shfl_sync(FULLMASK, ck, pos2 & 31);
            if (tk2) buf = got2;
        }
        bcnt = left;
    }
}

__global__ void __launch_bounds__(1024) knn_kernel(const float* __restrict__ xyz)
{
    extern __shared__ float4 spts[];    // [NN] : x, y, z, |p|^2  (128KB)
    __shared__ double s_p1[32], s_p2[32];

    const int b  = blockIdx.x >> 3;     // 8 query-chunks (128 queries) per batch
    const int qc = blockIdx.x & 7;
    const float* X = xyz + (size_t)b * NN * 3;

    for (int p = threadIdx.x; p < NN; p += 1024) {
        float x = X[p * 3], y = X[p * 3 + 1], z = X[p * 3 + 2];
        float sq = __fadd_rn(__fadd_rn(__fmul_rn(x, x), __fmul_rn(y, y)),
                             __fmul_rn(z, z));
        spts[p] = make_float4(x, y, z, sq);
    }
    __syncthreads();

    const int warp = threadIdx.x >> 5;
    const int lane = threadIdx.x & 31;
    const ull m2two = pk2(-2.0f, -2.0f);

    double acc1 = 0.0, acc2 = 0.0;      // meaningful on lane 0 only

    for (int qi = 0; qi < 4; qi++) {
        const int s = qc * 128 + warp * 4 + qi;
        const float* cen = g_newxyz + (size_t)(b * SS + s) * 3;
        const float cx = cen[0], cy = cen[1], cz = cen[2];
        const float csq = __fadd_rn(__fadd_rn(__fmul_rn(cx, cx), __fmul_rn(cy, cy)),
                                    __fmul_rn(cz, cz));
        const ull cX2 = pk2(cx, cx), cY2 = pk2(cy, cy), cZ2 = pk2(cz, cz);
        const ull csq2 = pk2(csq, csq);

        // init list from candidates 0..63 (sort first 32, merge next 32)
        ull key;
        {
            float4 pt = spts[lane];
            float dot = __fadd_rn(__fadd_rn(__fmul_rn(pt.x, cx), __fmul_rn(pt.y, cy)),
                                  __fmul_rn(pt.z, cz));
            float d = __fadd_rn(__fadd_rn(__fmul_rn(-2.0f, dot), csq), pt.w);
            key = sort32(makekey(d, lane), lane);
            float4 p2 = spts[32 + lane];
            float dot2 = __fadd_rn(__fadd_rn(__fmul_rn(p2.x, cx), __fmul_rn(p2.y, cy)),
                                   __fmul_rn(p2.z, cz));
            float dB = __fadd_rn(__fadd_rn(__fmul_rn(-2.0f, dot2), csq), p2.w);
            key = merge32(key, makekey(dB, 32 + lane), lane);
        }
        ull kth = __shfl_sync(FULLMASK, key, 31);
        ull buf = ~0ull;
        int bcnt = 0;

        for (int base = 64; base < NN; base += 64) {
            const int p0 = base + lane;
            const int p1 = base + 32 + lane;
            float4 a = spts[p0];
            float4 c = spts[p1];
            ull X2 = pk2(a.x, c.x), Y2 = pk2(a.y, c.y);
            ull Z2 = pk2(a.z, c.z), W2 = pk2(a.w, c.w);
            ull dot2 = add2(add2(mul2(X2, cX2), mul2(Y2, cY2)), mul2(Z2, cZ2));
            ull d2 = add2(add2(mul2(m2two, dot2), csq2), W2);
            float d0, d1;
            upk2(d0, d1, d2);
            ull k0 = makekey(d0, p0);
            ull k1 = makekey(d1, p1);
            unsigned h0 = __ballot_sync(FULLMASK, k0 < kth);
            unsigned h1 = __ballot_sync(FULLMASK, k1 < kth);
            if (h0) push_chunk(k0, h0, lane, key, kth, buf, bcnt);
            if (h1) {
                // re-filter under possibly-updated kth (extra entries harmless,
                // but must re-ballot for correct ranks)
                h1 = __ballot_sync(FULLMASK, k1 < kth);
                if (h1) push_chunk(k1, h1, lane, key, kth, buf, bcnt);
            }
        }
        if (bcnt > 0) key = merge32(key, buf, lane);   // empty slots hold MAX

        // ----- group stats over the kept 32 neighbors -----
        int ki = (int)(key & 0x1FFFull);
        float4 q = spts[ki];
        float dx = __fsub_rn(q.x, cx);
        float dy = __fsub_rn(q.y, cy);
        float dz = __fsub_rn(q.z, cz);
        float sdx = dx, sdy = dy, sdz = dz;
        float mdx = dx, mdy = dy, mdz = dz;
        float s1 = dx + dy + dz;
        float s2 = dx * dx + dy * dy + dz * dz;
#pragma unroll
        for (int o = 16; o; o >>= 1) {
            sdx += __shfl_down_sync(FULLMASK, sdx, o);
            sdy += __shfl_down_sync(FULLMASK, sdy, o);
            sdz += __shfl_down_sync(FULLMASK, sdz, o);
            mdx = fmaxf(mdx, __shfl_down_sync(FULLMASK, mdx, o));
            mdy = fmaxf(mdy, __shfl_down_sync(FULLMASK, mdy, o));
            mdz = fmaxf(mdz, __shfl_down_sync(FULLMASK, mdz, o));
            s1 += __shfl_down_sync(FULLMASK, s1, o);
            s2 += __shfl_down_sync(FULLMASK, s2, o);
        }
        if (lane == 0) {
            int ix = (b * SS + s) * 3;
            g_gsum[ix] = sdx; g_gsum[ix + 1] = sdy; g_gsum[ix + 2] = sdz;
            g_gmax[ix] = mdx; g_gmax[ix + 1] = mdy; g_gmax[ix + 2] = mdz;
            acc1 += (double)s1;
            acc2 += (double)s2;
        }
    }

    // one atomicAdd pair per block
    if (lane == 0) { s_p1[warp] = acc1; s_p2[warp] = acc2; }
    __syncthreads();
    if (threadIdx.x == 0) {
        double a = 0.0, c = 0.0;
        for (int w = 0; w < 32; w++) { a += s_p1[w]; c += s_p2[w]; }
        atomicAdd(&g_acc[0], a);
        atomicAdd(&g_acc[1], c);
    }
}

// =====================================================================
// K3: std, lc, BN1+relu, safe_cdist, BN2+relu. Single block.
// =====================================================================
__global__ void __launch_bounds__(1024) finalize_kernel(
    const float* __restrict__ bn1g, const float* __restrict__ bn1b,
    const float* __restrict__ bn2g, const float* __restrict__ bn2b,
    float* __restrict__ out)
{
    const int t = threadIdx.x;
    const int lane = t & 31, warp = t >> 5;

    __shared__ float s_red[32];
    __shared__ float s_se;
    __shared__ float s_mean[6], s_var[6];
    __shared__ float s_tf[BB * 36];
    __shared__ float s_m2[36], s_v2[36];

    if (t == 0) {
        double M = (double)BB * SS * KK * 3;
        double var = (g_acc[1] - g_acc[0] * g_acc[0] / M) / (M - 1.0); // ddof=1
        s_se = (float)sqrt(var) + 1e-5f;
    }
    __syncthreads();
    const float se = s_se;

    for (int idx = t; idx < BB * SS; idx += 1024) {
        int b = idx >> 10, s = idx & (SS - 1);
        const float* gm = g_gmax + idx * 3;
        const float* gs = g_gsum + idx * 3;
        const float* cn = g_newxyz + idx * 3;
#pragma unroll
        for (int c = 0; c < 3; c++) {
            float mx = __fdiv_rn(gm[c], se);
            float mn = __fdiv_rn(__fdiv_rn(gs[c], 32.0f), se);
            g_lc[(b * 6 + c) * SS + s] = __fadd_rn(mx, mn);
        }
#pragma unroll
        for (int c = 0; c < 3; c++) {
            float v = cn[c];
            g_lc[(b * 6 + 3 + c) * SS + s] = v + v;
        }
    }
    __syncthreads();

    for (int c = 0; c < 6; c++) {
        float part = 0.0f;
        for (int i = t; i < BB * SS; i += 1024) {
            int b = i >> 10, s = i & 1023;
            part += g_lc[(b * 6 + c) * SS + s];
        }
#pragma unroll
        for (int o = 16; o; o >>= 1) part += __shfl_down_sync(FULLMASK, part, o);
        if (lane == 0) s_red[warp] = part;
        __syncthreads();
        if (t == 0) {
            float tot = 0.0f;
            for (int w = 0; w < 32; w++) tot += s_red[w];
            s_mean[c] = tot / (float)(BB * SS);
        }
        __syncthreads();
        float m = s_mean[c];
        part = 0.0f;
        for (int i = t; i < BB * SS; i += 1024) {
            int b = i >> 10, s = i & 1023;
            float d = g_lc[(b * 6 + c) * SS + s] - m;
            part += d * d;
        }
#pragma unroll
        for (int o = 16; o; o >>= 1) part += __shfl_down_sync(FULLMASK, part, o);
        if (lane == 0) s_red[warp] = part;
        __syncthreads();
        if (t == 0) {
            float tot = 0.0f;
            for (int w = 0; w < 32; w++) tot += s_red[w];
            s_var[c] = tot / (float)(BB * SS);   // biased, as in reference
        }
        __syncthreads();
    }
    for (int c = 0; c < 6; c++) {
        float m = s_mean[c], v = s_var[c];
        float g = bn1g[c], bt = bn1b[c];
        float den = sqrtf(v + 1e-5f);
        for (int i = t; i < BB * SS; i += 1024) {
            int b = i >> 10, s = i & 1023;
            int ix = (b * 6 + c) * SS + s;
            float y = (g_lc[ix] - m) / den * g + bt;
            g_lc[ix] = fmaxf(y, 0.0f);
        }
    }
    __syncthreads();

    if (t < BB * 6) {
        int b = t / 6, c = t % 6;
        s_tf[b * 36 + c * 6 + c] = 0.0f;
    }
    for (int task = warp; task < BB * 15; task += 32) {
        int b = task / 15, pr = task % 15;
        int i = 0, j = 0, p = pr;
        for (i = 0; i < 5; i++) {
            int row = 5 - i;
            if (p < row) { j = i + 1 + p; break; }
            p -= row;
        }
        const float* A  = g_lc + (b * 6 + i) * SS;
        const float* Bp = g_lc + (b * 6 + j) * SS;
        float part = 0.0f;
        for (int s = lane; s < SS; s += 32) {
            float d = A[s] - Bp[s];
            part += d * d;
        }
#pragma unroll
        for (int o = 16; o; o >>= 1) part += __shfl_down_sync(FULLMASK, part, o);
        if (lane == 0) {
            float v = part > 0.0f ? sqrtf(part) : 0.0f;
            s_tf[b * 36 + i * 6 + j] = v;
            s_tf[b * 36 + j * 6 + i] = v;
        }
    }
    __syncthreads();

    if (t < 36) {
        float m = 0.0f;
        for (int b = 0; b < BB; b++) m += s_tf[b * 36 + t];
        m /= (float)BB;
        float v = 0.0f;
        for (int b = 0; b < BB; b++) {
            float d = s_tf[b * 36 + t] - m;
            v += d * d;
        }
        v /= (float)BB;
        s_m2[t] = m; s_v2[t] = v;
    }
    __syncthreads();
    if (t < BB * 36) {
        int b = t / 36, f = t % 36;
        float x = s_tf[b * 36 + f];
        float y = (x - s_m2[f]) / sqrtf(s_v2[f] + 1e-5f) * bn2g[f] + bn2b[f];
        out[t] = fmaxf(y, 0.0f);
    }
}

// =====================================================================
extern "C" void kernel_launch(void* const* d_in, const int* in_sizes, int n_in,
                              void* d_out, int out_size)
{
    const float* xyz  = (const float*)d_in[0];
    const float* bn1g = (const float*)d_in[1];
    const float* bn1b = (const float*)d_in[2];
    const float* bn2g = (const float*)d_in[3];
    const float* bn2b = (const float*)d_in[4];
    float* out = (float*)d_out;

    // idempotent host-side attribute set (capture-safe)
    cudaFuncSetAttribute(knn_kernel, cudaFuncAttributeMaxDynamicSharedMemorySize,
                         NN * (int)sizeof(float4));

    fps_kernel<<<BB, 1024>>>(xyz);
    knn_kernel<<<BB * 8, 1024, NN * sizeof(float4)>>>(xyz);
    finalize_kernel<<<1, 1024>>>(bn1g, bn1b, bn2g, bn2b, out);
}